// round 15
// baseline (speedup 1.0000x reference)
#include <cuda_runtime.h>
#include <math.h>

// Problem constants (fixed by the reference).
#define CC 128      // channels
#define WW 8        // hidden width
#define BB 8        // batch
#define TT 16000    // time

// LUT parameters
#define NTAB 1024                 // segments; float2 -> 8 KB smem; PWL err ~7e-6
#define XLO (-9.0f)
#define XHI (9.0f)

#define TPB 256                   // threads per block
#define SEGT (NTAB / TPB)         // 4 segments per thread in the prologue

// weight layout in smem: w1[0:8) b1[8:16) w2[16:80) b2[80:88) w3[88:96) b3[96]
#define OW1 0
#define OB1 8
#define OW2 16
#define OB2 80
#define OW3 88
#define OB3 96

// ---------------- fast per-channel MLP (prologue table build) --------------
__device__ __forceinline__ float ex2a(float a) {
    float e;
    asm("ex2.approx.f32 %0, %1;" : "=f"(e) : "f"(a));
    return e;
}
#define LOG2E 1.44269504088896340736f

__device__ __forceinline__ float elu_f(float y) {
    float e = ex2a(y * LOG2E) - 1.0f;
    return y > 0.0f ? y : e;
}

// Evaluate the channel MLP reading weights from shared memory (broadcast LDS).
// Live registers: h1[8], h2[8], a few temps — ~25 regs, no big arrays.
__device__ float mlp_eval_s(float xg, const float* __restrict__ ws) {
    float h1[WW], h2[WW];
#pragma unroll
    for (int v = 0; v < WW; v++)
        h1[v] = elu_f(fmaf(ws[OW1 + v], xg, ws[OB1 + v]));
#pragma unroll
    for (int v = 0; v < WW; v++) {
        float a = ws[OB2 + v];
#pragma unroll
        for (int w = 0; w < WW; w++)
            a = fmaf(ws[OW2 + v * WW + w], h1[w], a);
        h2[v] = elu_f(a);
    }
    float a = ws[OB3];
#pragma unroll
    for (int v = 0; v < WW; v++)
        a = fmaf(ws[OW3 + v], h2[v], a);
    return elu_f(a);
}

// ---------------- fused kernel: build channel LUT in smem, then stream -----
__device__ __forceinline__ float lut1(float xv, const float2* __restrict__ stab,
                                      float invH, float uoff, float umax) {
    float u = fmaf(xv, invH, uoff);
    u = fminf(fmaxf(u, 0.0f), umax);
    int i = (int)u;                   // u >= 0 -> trunc == floor
    float2 sc = stab[i];              // LDS.64: {slope, intercept-in-u}
    return fmaf(sc.x, u, sc.y);
}

__global__ void __launch_bounds__(TPB, 6)
tnl_kernel(const float* __restrict__ x,
           const float* __restrict__ w1, const float* __restrict__ b1,
           const float* __restrict__ w2, const float* __restrict__ b2,
           const float* __restrict__ w3, const float* __restrict__ b3,
           float* __restrict__ out) {
    __shared__ float2 stab[NTAB];     // 8 KB
    __shared__ float  ws[104];        // channel weights (97 used)

    const int row = blockIdx.x;       // row = b*CC + c, one full row per block
    const int c   = row & (CC - 1);
    const int t   = threadIdx.x;

    // stage weights into smem (one element per thread, 97 threads)
    if (t < WW) {
        ws[OW1 + t] = __ldg(w1 + c * WW + t);
        ws[OB1 + t] = __ldg(b1 + c * WW + t);
        ws[OB2 + t] = __ldg(b2 + c * WW + t);
        ws[OW3 + t] = __ldg(w3 + c * WW + t);
    } else if (t >= 32 && t < 96) {
        ws[OW2 + (t - 32)] = __ldg(w2 + c * WW * WW + (t - 32));
    } else if (t >= 96 && t < 128) {
        int k = t - 96;
        if (k < 32) {
            if (k == 0) ws[OB3] = __ldg(b3 + c);
            if (k >= 1 && k <= 32 && k - 1 + 32 < 64)
                ;  // (w2 upper half handled below)
        }
    }
    // w2 elements 32..63 by threads 128..159
    if (t >= 128 && t < 160)
        ws[OW2 + 32 + (t - 128)] = __ldg(w2 + c * WW * WW + 32 + (t - 128));
    __syncthreads();

    // ---- prologue: build this channel's PWL table (4 segments per thread) --
    {
        const float H = (XHI - XLO) / (float)NTAB;
        const int s0 = t * SEGT;

        float yprev = mlp_eval_s(XLO + (float)s0 * H, ws);
#pragma unroll
        for (int k = 1; k <= SEGT; k++) {
            float ycur = mlp_eval_s(XLO + (float)(s0 + k) * H, ws);
            float s = ycur - yprev;
            int  i = s0 + k - 1;
            stab[i] = make_float2(s, fmaf(-s, (float)i, yprev));
            yprev = ycur;
        }
    }
    __syncthreads();

    // ---- main stream: 1 LDS.64 + 2 FFMA per element ------------------------
    const float invH = (float)NTAB / (XHI - XLO);
    const float uoff = -XLO * invH;
    const float umax = (float)NTAB - 0.001f;

    const size_t base = (size_t)row * TT;
    const float4* __restrict__ xin  = (const float4*)(x + base);
    float4* __restrict__       oout = (float4*)(out + base);
    const int n4 = TT / 4;            // 4000

#pragma unroll 2
    for (int i = t; i < n4; i += TPB) {
        float4 v = __ldcs(xin + i);   // streaming read (touched once)
        float4 r;
        r.x = lut1(v.x, stab, invH, uoff, umax);
        r.y = lut1(v.y, stab, invH, uoff, umax);
        r.z = lut1(v.z, stab, invH, uoff, umax);
        r.w = lut1(v.w, stab, invH, uoff, umax);
        __stcs(oout + i, r);          // streaming write
    }
}

extern "C" void kernel_launch(void* const* d_in, const int* in_sizes, int n_in,
                              void* d_out, int out_size) {
    const float* x  = (const float*)d_in[0];
    const float* w1 = (const float*)d_in[1];
    const float* b1 = (const float*)d_in[2];
    const float* w2 = (const float*)d_in[3];
    const float* b2 = (const float*)d_in[4];
    const float* w3 = (const float*)d_in[5];
    const float* b3 = (const float*)d_in[6];
    float* out = (float*)d_out;

    tnl_kernel<<<BB * CC, TPB>>>(x, w1, b1, w2, b2, w3, b3, out);
}

// round 16
// speedup vs baseline: 3.9231x; 3.9231x over previous
#include <cuda_runtime.h>
#include <cuda_fp16.h>
#include <math.h>

// Problem constants (fixed by the reference).
#define CC 128      // channels
#define WW 8        // hidden width
#define BB 8        // batch
#define TT 16000    // time

// LUT parameters. Error budget: fp16 y0 quantization ~2e-4 dominates; PWL h^2
// error at NTAB=1024 is ~7e-6. So small table, 4B entries.
#define NTAB 1024
#define XLO (-9.0f)
#define XHI (9.0f)

#define TPB 256                   // threads per block (main kernel)
#define BTPB 256                  // threads per block (build kernel)
#define BSEGS (NTAB / BTPB)       // 4 segments per thread in build

// Per-channel PWL tables: entry i = half2{slope_i, y0_i} with
//   F(x) ~= y0_i + slope_i * (u - i),  u = (x - XLO) * NTAB/(XHI-XLO)
__device__ __half2 g_tab[CC * NTAB];

// ---------------- fast per-channel MLP (table build only) -----------------
__device__ __forceinline__ float ex2a(float a) {
    float e;
    asm("ex2.approx.f32 %0, %1;" : "=f"(e) : "f"(a));
    return e;
}
#define LOG2E 1.44269504088896340736f

__device__ __forceinline__ float elu_f(float y) {
    float e = ex2a(y * LOG2E) - 1.0f;
    return y > 0.0f ? y : e;
}

// Build: one block per channel; each thread holds the 97 channel weights in
// REGISTERS (proven fast path) and evaluates 5 grid points -> 4 entries.
__global__ void __launch_bounds__(BTPB)
build_kernel(const float* __restrict__ w1, const float* __restrict__ b1,
             const float* __restrict__ w2, const float* __restrict__ b2,
             const float* __restrict__ w3, const float* __restrict__ b3) {
    const int c  = blockIdx.x;
    const int s0 = threadIdx.x * BSEGS;               // first segment

    float rw1[WW], rb1[WW], rw2[WW * WW], rb2[WW], rw3[WW];
#pragma unroll
    for (int v = 0; v < WW; v++) {
        rw1[v] = __ldg(w1 + c * WW + v);
        rb1[v] = __ldg(b1 + c * WW + v);
        rb2[v] = __ldg(b2 + c * WW + v);
        rw3[v] = __ldg(w3 + c * WW + v);
    }
#pragma unroll
    for (int k = 0; k < WW * WW; k++)
        rw2[k] = __ldg(w2 + c * WW * WW + k);
    const float rb3 = __ldg(b3 + c);

    const float H = (XHI - XLO) / (float)NTAB;

    float y[BSEGS + 1];
#pragma unroll
    for (int k = 0; k <= BSEGS; k++) {
        float xg = XLO + (float)(s0 + k) * H;
        float h1[WW], h2[WW];
#pragma unroll
        for (int v = 0; v < WW; v++)
            h1[v] = elu_f(fmaf(rw1[v], xg, rb1[v]));
#pragma unroll
        for (int v = 0; v < WW; v++) {
            float a = rb2[v];
#pragma unroll
            for (int w = 0; w < WW; w++)
                a = fmaf(rw2[v * WW + w], h1[w], a);
            h2[v] = elu_f(a);
        }
        float a = rb3;
#pragma unroll
        for (int v = 0; v < WW; v++)
            a = fmaf(rw3[v], h2[v], a);
        y[k] = elu_f(a);
    }

    __half2* ot = g_tab + (size_t)c * NTAB + s0;
#pragma unroll
    for (int k = 0; k < BSEGS; k++) {
        float s = y[k + 1] - y[k];
        ot[k] = __halves2half2(__float2half_rn(s), __float2half_rn(y[k]));
    }
}

// ---------------- main streaming kernel -----------------------------------
__device__ __forceinline__ float lut1(float xv, const __half2* __restrict__ stab,
                                      float invH, float uoff, float umax) {
    float u = fmaf(xv, invH, uoff);
    u = fminf(fmaxf(u, 0.0f), umax);
    int i = (int)u;                    // u >= 0 -> trunc == floor
    float fi = (float)i;
    float2 sc = __half22float2(stab[i]);   // LDS.32: {slope, y0}
    return fmaf(sc.x, u - fi, sc.y);
}

__global__ void __launch_bounds__(TPB)
tnl_kernel(const float* __restrict__ x, float* __restrict__ out) {
    __shared__ __half2 stab[NTAB];     // 4 KB

    const int row = blockIdx.x;        // row = b*CC + c, one full row per block
    const int c   = row & (CC - 1);

    // copy this channel's table into smem (256 float4s)
    {
        const float4* src = (const float4*)(g_tab + (size_t)c * NTAB);
        float4* dst = (float4*)stab;
        if (threadIdx.x < NTAB / 4)
            dst[threadIdx.x] = __ldg(src + threadIdx.x);
    }
    __syncthreads();

    const float invH = (float)NTAB / (XHI - XLO);
    const float uoff = -XLO * invH;
    const float umax = (float)NTAB - 0.001f;

    const size_t base = (size_t)row * TT;
    const float4* __restrict__ xin  = (const float4*)(x + base);
    float4* __restrict__       oout = (float4*)(out + base);
    const int n4 = TT / 4;             // 4000

#pragma unroll 2
    for (int i = threadIdx.x; i < n4; i += TPB) {
        float4 v = __ldcs(xin + i);    // streaming read (touched once)
        float4 r;
        r.x = lut1(v.x, stab, invH, uoff, umax);
        r.y = lut1(v.y, stab, invH, uoff, umax);
        r.z = lut1(v.z, stab, invH, uoff, umax);
        r.w = lut1(v.w, stab, invH, uoff, umax);
        __stcs(oout + i, r);           // streaming write
    }
}

extern "C" void kernel_launch(void* const* d_in, const int* in_sizes, int n_in,
                              void* d_out, int out_size) {
    const float* x  = (const float*)d_in[0];
    const float* w1 = (const float*)d_in[1];
    const float* b1 = (const float*)d_in[2];
    const float* w2 = (const float*)d_in[3];
    const float* b2 = (const float*)d_in[4];
    const float* w3 = (const float*)d_in[5];
    const float* b3 = (const float*)d_in[6];
    float* out = (float*)d_out;

    build_kernel<<<CC, BTPB>>>(w1, b1, w2, b2, w3, b3);
    tnl_kernel<<<BB * CC, TPB>>>(x, out);
}

// round 17
// speedup vs baseline: 4.2349x; 1.0795x over previous
#include <cuda_runtime.h>
#include <cuda_fp16.h>
#include <math.h>

// Problem constants (fixed by the reference).
#define CC 128      // channels
#define WW 8        // hidden width
#define BB 8        // batch
#define TT 16000    // time

// LUT parameters. Error budget: fp16 y0 quantization ~2.1e-4 dominates (measured);
// PWL h^2 error at NTAB=512 is ~2.8e-5 (scaled from measured 6.86e-6 @1024).
#define NTAB 512
#define XLO (-9.0f)
#define XHI (9.0f)

#define TPB 256                   // threads per block (main kernel)
#define BTPB 128                  // threads per block (build kernel)
#define BSEGS (NTAB / BTPB)       // 4 segments per thread in build

// Per-channel PWL tables: entry i = half2{slope_i, y0_i} with
//   F(x) ~= y0_i + slope_i * (u - i),  u = (x - XLO) * NTAB/(XHI-XLO)
__device__ __half2 g_tab[CC * NTAB];

// ---------------- fast per-channel MLP (table build only) -----------------
__device__ __forceinline__ float ex2a(float a) {
    float e;
    asm("ex2.approx.f32 %0, %1;" : "=f"(e) : "f"(a));
    return e;
}
#define LOG2E 1.44269504088896340736f

__device__ __forceinline__ float elu_f(float y) {
    float e = ex2a(y * LOG2E) - 1.0f;
    return y > 0.0f ? y : e;
}

// Build: one block per channel; each thread holds the 97 channel weights in
// registers (proven fast path) and evaluates 5 grid points -> 4 entries.
__global__ void __launch_bounds__(BTPB)
build_kernel(const float* __restrict__ w1, const float* __restrict__ b1,
             const float* __restrict__ w2, const float* __restrict__ b2,
             const float* __restrict__ w3, const float* __restrict__ b3) {
    const int c  = blockIdx.x;
    const int s0 = threadIdx.x * BSEGS;               // first segment

    float rw1[WW], rb1[WW], rw2[WW * WW], rb2[WW], rw3[WW];
#pragma unroll
    for (int v = 0; v < WW; v++) {
        rw1[v] = __ldg(w1 + c * WW + v);
        rb1[v] = __ldg(b1 + c * WW + v);
        rb2[v] = __ldg(b2 + c * WW + v);
        rw3[v] = __ldg(w3 + c * WW + v);
    }
#pragma unroll
    for (int k = 0; k < WW * WW; k++)
        rw2[k] = __ldg(w2 + c * WW * WW + k);
    const float rb3 = __ldg(b3 + c);

    const float H = (XHI - XLO) / (float)NTAB;

    float y[BSEGS + 1];
#pragma unroll
    for (int k = 0; k <= BSEGS; k++) {
        float xg = XLO + (float)(s0 + k) * H;
        float h1[WW], h2[WW];
#pragma unroll
        for (int v = 0; v < WW; v++)
            h1[v] = elu_f(fmaf(rw1[v], xg, rb1[v]));
#pragma unroll
        for (int v = 0; v < WW; v++) {
            float a = rb2[v];
#pragma unroll
            for (int w = 0; w < WW; w++)
                a = fmaf(rw2[v * WW + w], h1[w], a);
            h2[v] = elu_f(a);
        }
        float a = rb3;
#pragma unroll
        for (int v = 0; v < WW; v++)
            a = fmaf(rw3[v], h2[v], a);
        y[k] = elu_f(a);
    }

    __half2* ot = g_tab + (size_t)c * NTAB + s0;
#pragma unroll
    for (int k = 0; k < BSEGS; k++) {
        float s = y[k + 1] - y[k];
        ot[k] = __halves2half2(__float2half_rn(s), __float2half_rn(y[k]));
    }
}

// ---------------- main streaming kernel -----------------------------------
__device__ __forceinline__ float lut1(float xv, const __half2* __restrict__ stab,
                                      float invH, float uoff, float umax) {
    float u = fmaf(xv, invH, uoff);
    u = fminf(fmaxf(u, 0.0f), umax);
    int i = (int)u;                    // u >= 0 -> trunc == floor
    float fi = (float)i;
    float2 sc = __half22float2(stab[i]);   // LDS.32: {slope, y0}
    return fmaf(sc.x, u - fi, sc.y);
}

__device__ __forceinline__ float4 lut4(float4 v, const __half2* __restrict__ stab,
                                       float invH, float uoff, float umax) {
    float4 r;
    r.x = lut1(v.x, stab, invH, uoff, umax);
    r.y = lut1(v.y, stab, invH, uoff, umax);
    r.z = lut1(v.z, stab, invH, uoff, umax);
    r.w = lut1(v.w, stab, invH, uoff, umax);
    return r;
}

__global__ void __launch_bounds__(TPB)
tnl_kernel(const float* __restrict__ x, float* __restrict__ out) {
    __shared__ __half2 stab[NTAB];     // 2 KB

    const int row = blockIdx.x;        // row = b*CC + c, one full row per block
    const int c   = row & (CC - 1);
    const int t   = threadIdx.x;

    // copy this channel's table into smem (128 float4s)
    {
        const float4* src = (const float4*)(g_tab + (size_t)c * NTAB);
        float4* dst = (float4*)stab;
        if (t < NTAB / 4)
            dst[t] = __ldg(src + t);
    }
    __syncthreads();

    const float invH = (float)NTAB / (XHI - XLO);
    const float uoff = -XLO * invH;
    const float umax = (float)NTAB - 0.001f;

    const size_t base = (size_t)row * TT;
    const float4* __restrict__ xin  = (const float4*)(x + base);
    float4* __restrict__       oout = (float4*)(out + base);
    const int n4 = TT / 4;             // 4000

    // Batched main loop: 4 in-flight LDG.128 per thread for MLP.
    int i = t;
    for (; i + 3 * TPB < n4; i += 4 * TPB) {
        float4 v0 = __ldcs(xin + i);
        float4 v1 = __ldcs(xin + i + TPB);
        float4 v2 = __ldcs(xin + i + 2 * TPB);
        float4 v3 = __ldcs(xin + i + 3 * TPB);
        float4 r0 = lut4(v0, stab, invH, uoff, umax);
        float4 r1 = lut4(v1, stab, invH, uoff, umax);
        float4 r2 = lut4(v2, stab, invH, uoff, umax);
        float4 r3 = lut4(v3, stab, invH, uoff, umax);
        __stcs(oout + i,           r0);
        __stcs(oout + i + TPB,     r1);
        __stcs(oout + i + 2 * TPB, r2);
        __stcs(oout + i + 3 * TPB, r3);
    }
    for (; i < n4; i += TPB) {
        float4 v = __ldcs(xin + i);
        __stcs(oout + i, lut4(v, stab, invH, uoff, umax));
    }
}

extern "C" void kernel_launch(void* const* d_in, const int* in_sizes, int n_in,
                              void* d_out, int out_size) {
    const float* x  = (const float*)d_in[0];
    const float* w1 = (const float*)d_in[1];
    const float* b1 = (const float*)d_in[2];
    const float* w2 = (const float*)d_in[3];
    const float* b2 = (const float*)d_in[4];
    const float* w3 = (const float*)d_in[5];
    const float* b3 = (const float*)d_in[6];
    float* out = (float*)d_out;

    build_kernel<<<CC, BTPB>>>(w1, b1, w2, b2, w3, b3);
    tnl_kernel<<<BB * CC, TPB>>>(x, out);
}